// round 1
// baseline (speedup 1.0000x reference)
#include <cuda_runtime.h>

#define NUM_PL 50000
#define NUM_TR 100000
#define NUM_AR 10000
#define OFF_TR NUM_PL
#define OFF_AR (NUM_PL + NUM_TR)
#define NTOT   (NUM_PL + NUM_TR + NUM_AR)
#define HID    64

// -------- scratch (device globals; no runtime allocation) --------
__device__ float g_x  [(size_t)NTOT * HID];   // layer input buffer A
__device__ float g_y  [(size_t)NTOT * HID];   // layer input buffer B
__device__ float g_agg[(size_t)NTOT * HID];   // neighbor-sum accumulator
__device__ int   g_deg [NTOT];
__device__ float g_rdeg[NTOT];

__device__ __forceinline__ void red_add_v4(float* a, float4 v) {
    asm volatile("red.global.add.v4.f32 [%0], {%1,%2,%3,%4};"
                 :: "l"(a), "f"(v.x), "f"(v.y), "f"(v.z), "f"(v.w)
                 : "memory");
}

// -------- init playlist & artist rows: emb + type_emb --------
__global__ void init_emb_kernel(const float* __restrict__ pl_emb,
                                const float* __restrict__ ar_emb,
                                const float* __restrict__ type_emb) {
    int t = blockIdx.x * blockDim.x + threadIdx.x;   // (NUM_PL+NUM_AR)*16 float4 chunks
    int total = (NUM_PL + NUM_AR) * (HID / 4);
    if (t >= total) return;
    int node = t >> 4;
    int c    = (t & 15) * 4;
    const float* src; float* dst; const float* ty;
    if (node < NUM_PL) {
        src = pl_emb + (size_t)node * HID;
        dst = g_x    + (size_t)node * HID;
        ty  = type_emb;                 // type 0
    } else {
        int a = node - NUM_PL;
        src = ar_emb + (size_t)a * HID;
        dst = g_x    + (size_t)(OFF_AR + a) * HID;
        ty  = type_emb + 2 * HID;       // type 2
    }
    float4 v  = *(const float4*)(src + c);
    float4 tv = *(const float4*)(ty  + c);
    v.x += tv.x; v.y += tv.y; v.z += tv.z; v.w += tv.w;
    *(float4*)(dst + c) = v;
}

// -------- zero agg (+ optionally deg) --------
__global__ void zero_kernel(int withDeg) {
    int t = blockIdx.x * blockDim.x + threadIdx.x;
    if (t < NTOT * (HID / 4))
        ((float4*)g_agg)[t] = make_float4(0.f, 0.f, 0.f, 0.f);
    if (withDeg && t < NTOT)
        g_deg[t] = 0;
}

// -------- degree counting: each undirected entry feeds both endpoints --------
__global__ void deg_kernel(const int* __restrict__ src, const int* __restrict__ dst,
                           int offS, int offD, int nE) {
    int e = blockIdx.x * blockDim.x + threadIdx.x;
    if (e >= nE) return;
    atomicAdd(&g_deg[__ldg(src + e) + offS], 1);
    atomicAdd(&g_deg[__ldg(dst + e) + offD], 1);
}

__global__ void rdeg_kernel() {
    int i = blockIdx.x * blockDim.x + threadIdx.x;
    if (i < NTOT) {
        int d = g_deg[i];
        g_rdeg[i] = 1.0f / (float)(d > 0 ? d : 1);
    }
}

// -------- scatter: both directions of each entry; 16 threads / entry --------
__global__ void scatter_kernel(const int* __restrict__ src, const int* __restrict__ dst,
                               int offS, int offD, int nE, int xSel) {
    const float* __restrict__ x = (xSel == 0) ? g_x : g_y;
    int t = blockIdx.x * blockDim.x + threadIdx.x;
    int total = nE * 16;
    if (t >= total) return;
    int e = t >> 4;
    int c = (t & 15) * 4;
    int a = __ldg(src + e) + offS;
    int b = __ldg(dst + e) + offD;
    float4 va = *(const float4*)(x + (size_t)a * HID + c);
    float4 vb = *(const float4*)(x + (size_t)b * HID + c);
    red_add_v4(g_agg + (size_t)b * HID + c, va);   // agg[dst] += x[src]
    red_add_v4(g_agg + (size_t)a * HID + c, vb);   // reverse direction
}

// -------- fused GEMM: out[n,o] = act( sum_k rowcat[n,k] * Wcat[o,k] + bias[o] (+bias2[o]) )
// rowcat = [A_row (*rdeg) | B_row]  (or a plain 128-wide A row when bSel<0)
// 128 threads, 32 nodes/block, 4 outputs x 4 nodes per thread, K split in 2 halves.
__global__ void gemm_kernel(const float* __restrict__ Aext, int aSel, int lda,
                            int bSel, int useRdeg,
                            const float* __restrict__ W0,   // 64x64 (if W1) else 64x128
                            const float* __restrict__ W1,   // nullable
                            const float* __restrict__ bias,
                            const float* __restrict__ bias2, // nullable
                            float* __restrict__ outExt, int outSel, int outRowOff,
                            int relu) {
    __shared__ float Ws[64][68];     // Ws[k][o], padded; rows stay 16B aligned (68*4=272)
    __shared__ float rows[32][132];  // rows[n][k], padded against ty-stride conflicts

    const float* __restrict__ A = (aSel == 2) ? g_agg : Aext;
    const float* __restrict__ B = (bSel == 0) ? g_x : (bSel == 1 ? g_y : nullptr);
    float* __restrict__ O = (outSel == 0) ? g_x : (outSel == 1 ? g_y : outExt);

    const int tid = threadIdx.x;     // 128
    const int tx  = tid & 15;        // output tile (4 outputs)
    const int ty  = tid >> 4;        // 0..7 node tile (4 nodes)
    const int nodeBase = blockIdx.x * 32;

    // stage 32 node rows of 128
    for (int idx = tid; idx < 32 * 128; idx += 128) {
        int n = idx >> 7, k = idx & 127;
        int node = nodeBase + n;
        float v;
        if (B) {
            if (k < HID) {
                v = A[(size_t)node * lda + k];
                if (useRdeg) v *= g_rdeg[node];
            } else {
                v = B[(size_t)node * HID + (k - HID)];
            }
        } else {
            v = A[(size_t)node * lda + k];
        }
        rows[n][k] = v;
    }

    float acc[4][4];
#pragma unroll
    for (int j = 0; j < 4; j++)
#pragma unroll
        for (int i = 0; i < 4; i++) acc[j][i] = 0.f;

    for (int h = 0; h < 2; h++) {
        __syncthreads();
        const float* Wsrc; int wstride, koff;
        if (W1) { Wsrc = (h == 0) ? W0 : W1; wstride = 64;  koff = 0; }
        else    { Wsrc = W0;                 wstride = 128; koff = h * 64; }
        for (int idx = tid; idx < 64 * 64; idx += 128) {
            int o = idx >> 6, k = idx & 63;           // coalesced global read over k
            Ws[k][o] = Wsrc[(size_t)o * wstride + koff + k];
        }
        __syncthreads();
#pragma unroll 4
        for (int k = 0; k < 64; k++) {
            float4 w = *(const float4*)&Ws[k][tx * 4];
#pragma unroll
            for (int j = 0; j < 4; j++) {
                float r = rows[ty * 4 + j][h * 64 + k];
                acc[j][0] = fmaf(r, w.x, acc[j][0]);
                acc[j][1] = fmaf(r, w.y, acc[j][1]);
                acc[j][2] = fmaf(r, w.z, acc[j][2]);
                acc[j][3] = fmaf(r, w.w, acc[j][3]);
            }
        }
    }

    const int o = tx * 4;
    float b0 = bias[o], b1 = bias[o + 1], b2 = bias[o + 2], b3 = bias[o + 3];
    if (bias2) { b0 += bias2[o]; b1 += bias2[o + 1]; b2 += bias2[o + 2]; b3 += bias2[o + 3]; }
#pragma unroll
    for (int j = 0; j < 4; j++) {
        int node = nodeBase + ty * 4 + j;
        float4 r;
        r.x = acc[j][0] + b0;
        r.y = acc[j][1] + b1;
        r.z = acc[j][2] + b2;
        r.w = acc[j][3] + b3;
        if (relu) {
            r.x = fmaxf(r.x, 0.f); r.y = fmaxf(r.y, 0.f);
            r.z = fmaxf(r.z, 0.f); r.w = fmaxf(r.w, 0.f);
        }
        *(float4*)(O + (size_t)(node + outRowOff) * HID + o) = r;
    }
}

extern "C" void kernel_launch(void* const* d_in, const int* in_sizes, int n_in,
                              void* d_out, int out_size) {
    const float* track_x   = (const float*)d_in[0];
    const int*   pl_tr_src = (const int*)d_in[1];
    const int*   pl_tr_dst = (const int*)d_in[2];
    const int*   tr_ar_src = (const int*)d_in[3];
    const int*   tr_ar_dst = (const int*)d_in[4];
    const float* pl_emb    = (const float*)d_in[5];
    const float* ar_emb    = (const float*)d_in[6];
    const float* track_W   = (const float*)d_in[7];
    const float* track_b   = (const float*)d_in[8];
    const float* type_emb  = (const float*)d_in[9];
    const float* conv_Wl   = (const float*)d_in[10];
    const float* conv_bl   = (const float*)d_in[11];
    const float* conv_Wr   = (const float*)d_in[12];
    float* out = (float*)d_out;

    const int E1 = in_sizes[1];   // pl<->tr entries (2,000,000)
    const int E2 = in_sizes[3];   // tr<->ar entries (100,000)

    // node features
    {
        int total = (NUM_PL + NUM_AR) * (HID / 4);
        init_emb_kernel<<<(total + 255) / 256, 256>>>(pl_emb, ar_emb, type_emb);
    }
    // track linear -> g_x rows [OFF_TR, OFF_TR+NUM_TR)
    gemm_kernel<<<NUM_TR / 32, 128>>>(track_x, /*aSel*/-1, /*lda*/128,
                                      /*bSel*/-1, /*useRdeg*/0,
                                      track_W, nullptr,
                                      track_b, type_emb + HID,
                                      nullptr, /*outSel*/0, /*outRowOff*/OFF_TR,
                                      /*relu*/0);

    // degrees (fixed across layers)
    zero_kernel<<<(NTOT * (HID / 4) + 255) / 256, 256>>>(1);
    deg_kernel<<<(E1 + 255) / 256, 256>>>(pl_tr_src, pl_tr_dst, 0, OFF_TR, E1);
    deg_kernel<<<(E2 + 255) / 256, 256>>>(tr_ar_src, tr_ar_dst, OFF_TR, OFF_AR, E2);
    rdeg_kernel<<<(NTOT + 255) / 256, 256>>>();

    // ---- layer 0: g_x -> g_y ----
    scatter_kernel<<<(E1 * 16 + 255) / 256, 256>>>(pl_tr_src, pl_tr_dst, 0, OFF_TR, E1, /*xSel*/0);
    scatter_kernel<<<(E2 * 16 + 255) / 256, 256>>>(tr_ar_src, tr_ar_dst, OFF_TR, OFF_AR, E2, 0);
    gemm_kernel<<<NTOT / 32, 128>>>(nullptr, /*aSel*/2, /*lda*/HID,
                                    /*bSel*/0, /*useRdeg*/1,
                                    conv_Wl, conv_Wr,
                                    conv_bl, nullptr,
                                    nullptr, /*outSel*/1, 0, /*relu*/1);

    // ---- layer 1: g_y -> d_out ----
    zero_kernel<<<(NTOT * (HID / 4) + 255) / 256, 256>>>(0);
    scatter_kernel<<<(E1 * 16 + 255) / 256, 256>>>(pl_tr_src, pl_tr_dst, 0, OFF_TR, E1, /*xSel*/1);
    scatter_kernel<<<(E2 * 16 + 255) / 256, 256>>>(tr_ar_src, tr_ar_dst, OFF_TR, OFF_AR, E2, 1);
    gemm_kernel<<<NTOT / 32, 128>>>(nullptr, /*aSel*/2, /*lda*/HID,
                                    /*bSel*/1, /*useRdeg*/1,
                                    conv_Wl + 64 * 64, conv_Wr + 64 * 64,
                                    conv_bl + 64, nullptr,
                                    out, /*outSel*/-1, 0, /*relu*/1);
}

// round 2
// speedup vs baseline: 1.5894x; 1.5894x over previous
#include <cuda_runtime.h>

#define NUM_PL 50000
#define NUM_TR 100000
#define NUM_AR 10000
#define OFF_TR NUM_PL
#define OFF_AR (NUM_PL + NUM_TR)
#define NTOT   (NUM_PL + NUM_TR + NUM_AR)
#define HID    64
#define NADJ   4200000          // 2*(2,000,000 + 100,000) directed edges
#define SCAN_B 1024
#define NB     ((NTOT + SCAN_B - 1) / SCAN_B)   // 157

typedef unsigned long long ull;

// -------- scratch (device globals; no runtime allocation) --------
__device__ float g_x  [(size_t)NTOT * HID];
__device__ float g_y  [(size_t)NTOT * HID];
__device__ float g_agg[(size_t)NTOT * HID];
__device__ int   g_deg [NTOT];
__device__ float g_rdeg[NTOT];
__device__ int   g_ptr [NTOT];
__device__ int   g_cur [NTOT];
__device__ int   g_adj [NADJ];
__device__ int   g_bsum[NB];
__device__ int   g_boff[NB];

// -------- packed f32x2 helpers (Blackwell) --------
__device__ __forceinline__ ull dup_f32(float x) {
    ull r; asm("mov.b64 %0, {%1,%1};" : "=l"(r) : "f"(x)); return r;
}
__device__ __forceinline__ void ffma2(ull& d, ull a, ull b) {
    asm("fma.rn.f32x2 %0, %1, %2, %3;" : "=l"(d) : "l"(a), "l"(b), "l"(d));
}
__device__ __forceinline__ float2 unpack2(ull v) {
    float2 f; asm("mov.b64 {%0,%1}, %2;" : "=f"(f.x), "=f"(f.y) : "l"(v)); return f;
}

// -------- init playlist & artist rows: emb + type_emb --------
__global__ void init_emb_kernel(const float* __restrict__ pl_emb,
                                const float* __restrict__ ar_emb,
                                const float* __restrict__ type_emb) {
    int t = blockIdx.x * blockDim.x + threadIdx.x;
    int total = (NUM_PL + NUM_AR) * (HID / 4);
    if (t >= total) return;
    int node = t >> 4;
    int c    = (t & 15) * 4;
    const float* src; float* dst; const float* ty;
    if (node < NUM_PL) {
        src = pl_emb + (size_t)node * HID;
        dst = g_x    + (size_t)node * HID;
        ty  = type_emb;
    } else {
        int a = node - NUM_PL;
        src = ar_emb + (size_t)a * HID;
        dst = g_x    + (size_t)(OFF_AR + a) * HID;
        ty  = type_emb + 2 * HID;
    }
    float4 v  = *(const float4*)(src + c);
    float4 tv = *(const float4*)(ty  + c);
    v.x += tv.x; v.y += tv.y; v.z += tv.z; v.w += tv.w;
    *(float4*)(dst + c) = v;
}

__global__ void zero_deg_kernel() {
    int i = blockIdx.x * blockDim.x + threadIdx.x;
    if (i < NTOT) g_deg[i] = 0;
}

__global__ void deg_kernel(const int* __restrict__ src, const int* __restrict__ dst,
                           int offS, int offD, int nE) {
    int e = blockIdx.x * blockDim.x + threadIdx.x;
    if (e >= nE) return;
    atomicAdd(&g_deg[__ldg(src + e) + offS], 1);
    atomicAdd(&g_deg[__ldg(dst + e) + offD], 1);
}

// -------- 3-pass exclusive scan of g_deg -> g_ptr / g_cur (+ rdeg) --------
__device__ __forceinline__ int block_incl_scan(int v, int* warpsums) {
    int lane = threadIdx.x & 31, wid = threadIdx.x >> 5;
    int x = v;
#pragma unroll
    for (int o = 1; o < 32; o <<= 1) {
        int y = __shfl_up_sync(0xffffffffu, x, o);
        if (lane >= o) x += y;
    }
    if (lane == 31) warpsums[wid] = x;
    __syncthreads();
    if (threadIdx.x < 32) {
        int w = warpsums[threadIdx.x];
#pragma unroll
        for (int o = 1; o < 32; o <<= 1) {
            int y = __shfl_up_sync(0xffffffffu, w, o);
            if (threadIdx.x >= o) w += y;
        }
        warpsums[threadIdx.x] = w;
    }
    __syncthreads();
    if (wid > 0) x += warpsums[wid - 1];
    return x;
}

__global__ void scan_pass1() {           // per-block sums
    __shared__ int warpsums[32];
    int i = blockIdx.x * SCAN_B + threadIdx.x;
    int v = (i < NTOT) ? g_deg[i] : 0;
    int x = block_incl_scan(v, warpsums);
    if (threadIdx.x == SCAN_B - 1) g_bsum[blockIdx.x] = x;
}

__global__ void scan_pass2() {           // scan the 157 block sums (1 block, 256 thr)
    __shared__ int warpsums[32];
    int i = threadIdx.x;
    int v = (i < NB) ? g_bsum[i] : 0;
    int x = block_incl_scan(v, warpsums);
    if (i < NB) g_boff[i] = x - v;       // exclusive
}

__global__ void scan_pass3() {           // write ptr/cur/rdeg
    __shared__ int warpsums[32];
    int i = blockIdx.x * SCAN_B + threadIdx.x;
    int v = (i < NTOT) ? g_deg[i] : 0;
    int x = block_incl_scan(v, warpsums);
    if (i < NTOT) {
        int excl = x - v + g_boff[blockIdx.x];
        g_ptr[i] = excl;
        g_cur[i] = excl;
        g_rdeg[i] = 1.0f / (float)(v > 0 ? v : 1);
    }
}

// -------- CSR fill: both directions per entry --------
__global__ void fill_kernel(const int* __restrict__ src, const int* __restrict__ dst,
                            int offS, int offD, int nE) {
    int e = blockIdx.x * blockDim.x + threadIdx.x;
    if (e >= nE) return;
    int a = __ldg(src + e) + offS;
    int b = __ldg(dst + e) + offD;
    int pa = atomicAdd(&g_cur[a], 1);
    g_adj[pa] = b;
    int pb = atomicAdd(&g_cur[b], 1);
    g_adj[pb] = a;
}

// -------- gather aggregation: 16 lanes per node, reg accumulation --------
__global__ void gather_kernel(int xSel) {
    const float* __restrict__ x = xSel ? g_y : g_x;
    int t = blockIdx.x * blockDim.x + threadIdx.x;
    int node = t >> 4;
    if (node >= NTOT) return;
    int c = (t & 15) * 4;
    int beg = g_ptr[node];
    int d   = g_deg[node];
    float4 acc = make_float4(0.f, 0.f, 0.f, 0.f);
    int i = 0;
    for (; i + 4 <= d; i += 4) {
        int s0 = __ldg(g_adj + beg + i);
        int s1 = __ldg(g_adj + beg + i + 1);
        int s2 = __ldg(g_adj + beg + i + 2);
        int s3 = __ldg(g_adj + beg + i + 3);
        float4 v0 = *(const float4*)(x + (size_t)s0 * HID + c);
        float4 v1 = *(const float4*)(x + (size_t)s1 * HID + c);
        float4 v2 = *(const float4*)(x + (size_t)s2 * HID + c);
        float4 v3 = *(const float4*)(x + (size_t)s3 * HID + c);
        acc.x += v0.x + v1.x + v2.x + v3.x;
        acc.y += v0.y + v1.y + v2.y + v3.y;
        acc.z += v0.z + v1.z + v2.z + v3.z;
        acc.w += v0.w + v1.w + v2.w + v3.w;
    }
    for (; i < d; i++) {
        int s = __ldg(g_adj + beg + i);
        float4 v = *(const float4*)(x + (size_t)s * HID + c);
        acc.x += v.x; acc.y += v.y; acc.z += v.z; acc.w += v.w;
    }
    float rd = g_rdeg[node];
    acc.x *= rd; acc.y *= rd; acc.z *= rd; acc.w *= rd;
    *(float4*)(g_agg + (size_t)node * HID + c) = acc;
}

// -------- fused GEMM with packed f32x2 FMAs --------
// out[n,o] = act( sum_k rowcat[n,k]*Wcat[o,k] + bias[o] (+bias2[o]) )
// rowcat = [agg_row | x_row] (bSel>=0) or plain 128-wide A row (bSel<0).
// 128 threads, 32 nodes/block; tx=output quad, ty=node quad. rows stored [k][n].
__global__ void __launch_bounds__(128) gemm_kernel(
        const float* __restrict__ Aext, int aSel, int lda, int bSel,
        const float* __restrict__ W0, const float* __restrict__ W1,
        const float* __restrict__ bias, const float* __restrict__ bias2,
        float* __restrict__ outExt, int outSel, int outRowOff, int relu) {
    __shared__ float Ws[64][68];     // Ws[k][o]; 272B row stride (16B aligned)
    __shared__ float rows[128][36];  // rows[k][n]; 144B row stride (16B aligned)

    const float* __restrict__ A = (aSel == 2) ? g_agg : Aext;
    const float* __restrict__ B = (bSel == 0) ? g_x : (bSel == 1 ? g_y : nullptr);
    float* __restrict__ O = (outSel == 0) ? g_x : (outSel == 1 ? g_y : outExt);

    const int tid = threadIdx.x;
    const int tx  = tid & 15;        // output quad: o = tx*4..tx*4+3
    const int ty  = tid >> 4;        // node quad: n = ty*4..ty*4+3
    const int nodeBase = blockIdx.x * 32;

    // stage 32 node rows, transposed: rows[k][n]
    for (int it = 0; it < 32; it++) {
        int node = nodeBase + it;
        int k = tid;                 // 0..127
        float v;
        if (B) v = (k < HID) ? A[(size_t)node * lda + k]
                             : B[(size_t)node * HID + (k - HID)];
        else   v = A[(size_t)node * lda + k];
        rows[k][it] = v;
    }

    ull a01[4], a23[4];              // [i]: node pairs (j0,j1)/(j2,j3), output tx*4+i
#pragma unroll
    for (int i = 0; i < 4; i++) { a01[i] = 0ull; a23[i] = 0ull; }

    for (int h = 0; h < 2; h++) {
        __syncthreads();
        const float* Wsrc; int wstride, koff;
        if (W1) { Wsrc = h ? W1 : W0; wstride = 64;  koff = 0; }
        else    { Wsrc = W0;          wstride = 128; koff = h * 64; }
        for (int idx = tid; idx < 64 * 64; idx += 128) {
            int o = idx >> 6, k = idx & 63;
            Ws[k][o] = Wsrc[(size_t)o * wstride + koff + k];
        }
        __syncthreads();
#pragma unroll 8
        for (int k = 0; k < 64; k++) {
            ulonglong2 rp = *(const ulonglong2*)&rows[(h << 6) + k][ty * 4];
            float4 w = *(const float4*)&Ws[k][tx * 4];
            ull w0 = dup_f32(w.x), w1 = dup_f32(w.y);
            ull w2 = dup_f32(w.z), w3 = dup_f32(w.w);
            ffma2(a01[0], rp.x, w0); ffma2(a23[0], rp.y, w0);
            ffma2(a01[1], rp.x, w1); ffma2(a23[1], rp.y, w1);
            ffma2(a01[2], rp.x, w2); ffma2(a23[2], rp.y, w2);
            ffma2(a01[3], rp.x, w3); ffma2(a23[3], rp.y, w3);
        }
    }

    const int o = tx * 4;
    float b0 = bias[o], b1 = bias[o + 1], b2 = bias[o + 2], b3 = bias[o + 3];
    if (bias2) { b0 += bias2[o]; b1 += bias2[o + 1]; b2 += bias2[o + 2]; b3 += bias2[o + 3]; }

    float res[4][4];                 // [j][i]
#pragma unroll
    for (int i = 0; i < 4; i++) {
        float2 p = unpack2(a01[i]);
        float2 q = unpack2(a23[i]);
        res[0][i] = p.x; res[1][i] = p.y; res[2][i] = q.x; res[3][i] = q.y;
    }
#pragma unroll
    for (int j = 0; j < 4; j++) {
        int node = nodeBase + ty * 4 + j;
        float4 r;
        r.x = res[j][0] + b0; r.y = res[j][1] + b1;
        r.z = res[j][2] + b2; r.w = res[j][3] + b3;
        if (relu) {
            r.x = fmaxf(r.x, 0.f); r.y = fmaxf(r.y, 0.f);
            r.z = fmaxf(r.z, 0.f); r.w = fmaxf(r.w, 0.f);
        }
        *(float4*)(O + (size_t)(node + outRowOff) * HID + o) = r;
    }
}

extern "C" void kernel_launch(void* const* d_in, const int* in_sizes, int n_in,
                              void* d_out, int out_size) {
    const float* track_x   = (const float*)d_in[0];
    const int*   pl_tr_src = (const int*)d_in[1];
    const int*   pl_tr_dst = (const int*)d_in[2];
    const int*   tr_ar_src = (const int*)d_in[3];
    const int*   tr_ar_dst = (const int*)d_in[4];
    const float* pl_emb    = (const float*)d_in[5];
    const float* ar_emb    = (const float*)d_in[6];
    const float* track_W   = (const float*)d_in[7];
    const float* track_b   = (const float*)d_in[8];
    const float* type_emb  = (const float*)d_in[9];
    const float* conv_Wl   = (const float*)d_in[10];
    const float* conv_bl   = (const float*)d_in[11];
    const float* conv_Wr   = (const float*)d_in[12];
    float* out = (float*)d_out;

    const int E1 = in_sizes[1];
    const int E2 = in_sizes[3];

    // node features
    {
        int total = (NUM_PL + NUM_AR) * (HID / 4);
        init_emb_kernel<<<(total + 255) / 256, 256>>>(pl_emb, ar_emb, type_emb);
    }
    gemm_kernel<<<NUM_TR / 32, 128>>>(track_x, -1, 128, /*bSel*/-1,
                                      track_W, nullptr,
                                      track_b, type_emb + HID,
                                      nullptr, /*outSel*/0, OFF_TR, /*relu*/0);

    // degrees + CSR (fixed across layers)
    zero_deg_kernel<<<(NTOT + 255) / 256, 256>>>();
    deg_kernel<<<(E1 + 255) / 256, 256>>>(pl_tr_src, pl_tr_dst, 0, OFF_TR, E1);
    deg_kernel<<<(E2 + 255) / 256, 256>>>(tr_ar_src, tr_ar_dst, OFF_TR, OFF_AR, E2);
    scan_pass1<<<NB, SCAN_B>>>();
    scan_pass2<<<1, 256>>>();
    scan_pass3<<<NB, SCAN_B>>>();
    fill_kernel<<<(E1 + 255) / 256, 256>>>(pl_tr_src, pl_tr_dst, 0, OFF_TR, E1);
    fill_kernel<<<(E2 + 255) / 256, 256>>>(tr_ar_src, tr_ar_dst, OFF_TR, OFF_AR, E2);

    // ---- layer 0: g_x -> g_y ----
    gather_kernel<<<(NTOT * 16 + 255) / 256, 256>>>(0);
    gemm_kernel<<<NTOT / 32, 128>>>(nullptr, 2, HID, /*bSel*/0,
                                    conv_Wl, conv_Wr, conv_bl, nullptr,
                                    nullptr, /*outSel*/1, 0, /*relu*/1);

    // ---- layer 1: g_y -> d_out ----
    gather_kernel<<<(NTOT * 16 + 255) / 256, 256>>>(1);
    gemm_kernel<<<NTOT / 32, 128>>>(nullptr, 2, HID, /*bSel*/1,
                                    conv_Wl + 64 * 64, conv_Wr + 64 * 64,
                                    conv_bl + 64, nullptr,
                                    out, /*outSel*/-1, 0, /*relu*/1);
}

// round 3
// speedup vs baseline: 1.7597x; 1.1071x over previous
#include <cuda_runtime.h>
#include <cuda_fp16.h>

#define NUM_PL 50000
#define NUM_TR 100000
#define NUM_AR 10000
#define OFF_TR NUM_PL
#define OFF_AR (NUM_PL + NUM_TR)
#define NTOT   (NUM_PL + NUM_TR + NUM_AR)
#define HID    64
#define NADJ   4200000          // 2*(2,000,000 + 100,000) directed edges
#define SCAN_B 1024
#define NB     ((NTOT + SCAN_B - 1) / SCAN_B)   // 157

typedef unsigned long long ull;

// -------- scratch (device globals; no runtime allocation) --------
__device__ __align__(16) float  g_x  [(size_t)NTOT * HID];
__device__ __align__(16) float  g_y  [(size_t)NTOT * HID];
__device__ __align__(16) float  g_agg[(size_t)NTOT * HID];
__device__ __align__(16) __half g_h  [(size_t)NTOT * HID];   // fp16 shadow of current features
__device__ int   g_deg [NTOT];
__device__ float g_rdeg[NTOT];
__device__ int   g_ptr [NTOT];
__device__ int   g_cur [NTOT];
__device__ int   g_adj [NADJ];
__device__ int   g_bsum[NB];
__device__ int   g_boff[NB];

// -------- packed f32x2 helpers (Blackwell) --------
__device__ __forceinline__ ull dup_f32(float x) {
    ull r; asm("mov.b64 %0, {%1,%1};" : "=l"(r) : "f"(x)); return r;
}
__device__ __forceinline__ void ffma2(ull& d, ull a, ull b) {
    asm("fma.rn.f32x2 %0, %1, %2, %3;" : "=l"(d) : "l"(a), "l"(b), "l"(d));
}
__device__ __forceinline__ float2 unpack2(ull v) {
    float2 f; asm("mov.b64 {%0,%1}, %2;" : "=f"(f.x), "=f"(f.y) : "l"(v)); return f;
}
__device__ __forceinline__ float2 h2f(unsigned u) {
    return __half22float2(*(const __half2*)&u);
}
__device__ __forceinline__ unsigned f2h2(float a, float b) {
    __half2 h = __floats2half2_rn(a, b);
    return *(const unsigned*)&h;
}

// -------- init playlist & artist rows: emb + type_emb (fp32 + fp16 shadow) --------
__global__ void init_emb_kernel(const float* __restrict__ pl_emb,
                                const float* __restrict__ ar_emb,
                                const float* __restrict__ type_emb) {
    int t = blockIdx.x * blockDim.x + threadIdx.x;
    int total = (NUM_PL + NUM_AR) * (HID / 4);
    if (t >= total) return;
    int node = t >> 4;
    int c    = (t & 15) * 4;
    const float* src; const float* ty; size_t row;
    if (node < NUM_PL) {
        src = pl_emb + (size_t)node * HID;
        row = (size_t)node * HID;
        ty  = type_emb;
    } else {
        int a = node - NUM_PL;
        src = ar_emb + (size_t)a * HID;
        row = (size_t)(OFF_AR + a) * HID;
        ty  = type_emb + 2 * HID;
    }
    float4 v  = *(const float4*)(src + c);
    float4 tv = *(const float4*)(ty  + c);
    v.x += tv.x; v.y += tv.y; v.z += tv.z; v.w += tv.w;
    *(float4*)(g_x + row + c) = v;
    uint2 h; h.x = f2h2(v.x, v.y); h.y = f2h2(v.z, v.w);
    *(uint2*)(g_h + row + c) = h;
}

__global__ void zero_deg_kernel() {
    int i = blockIdx.x * blockDim.x + threadIdx.x;
    if (i < NTOT) g_deg[i] = 0;
}

__global__ void deg_kernel(const int* __restrict__ src, const int* __restrict__ dst,
                           int offS, int offD, int nE) {
    int e = blockIdx.x * blockDim.x + threadIdx.x;
    if (e >= nE) return;
    atomicAdd(&g_deg[__ldg(src + e) + offS], 1);
    atomicAdd(&g_deg[__ldg(dst + e) + offD], 1);
}

// -------- 3-pass exclusive scan of g_deg -> g_ptr / g_cur (+ rdeg) --------
__device__ __forceinline__ int block_incl_scan(int v, int* warpsums) {
    int lane = threadIdx.x & 31, wid = threadIdx.x >> 5;
    int x = v;
#pragma unroll
    for (int o = 1; o < 32; o <<= 1) {
        int y = __shfl_up_sync(0xffffffffu, x, o);
        if (lane >= o) x += y;
    }
    if (lane == 31) warpsums[wid] = x;
    __syncthreads();
    if (threadIdx.x < 32) {
        int w = warpsums[threadIdx.x];
#pragma unroll
        for (int o = 1; o < 32; o <<= 1) {
            int y = __shfl_up_sync(0xffffffffu, w, o);
            if (threadIdx.x >= o) w += y;
        }
        warpsums[threadIdx.x] = w;
    }
    __syncthreads();
    if (wid > 0) x += warpsums[wid - 1];
    return x;
}

__global__ void scan_pass1() {
    __shared__ int warpsums[32];
    int i = blockIdx.x * SCAN_B + threadIdx.x;
    int v = (i < NTOT) ? g_deg[i] : 0;
    int x = block_incl_scan(v, warpsums);
    if (threadIdx.x == SCAN_B - 1) g_bsum[blockIdx.x] = x;
}

__global__ void scan_pass2() {
    __shared__ int warpsums[32];
    int i = threadIdx.x;
    int v = (i < NB) ? g_bsum[i] : 0;
    int x = block_incl_scan(v, warpsums);
    if (i < NB) g_boff[i] = x - v;
}

__global__ void scan_pass3() {
    __shared__ int warpsums[32];
    int i = blockIdx.x * SCAN_B + threadIdx.x;
    int v = (i < NTOT) ? g_deg[i] : 0;
    int x = block_incl_scan(v, warpsums);
    if (i < NTOT) {
        int excl = x - v + g_boff[blockIdx.x];
        g_ptr[i] = excl;
        g_cur[i] = excl;
        g_rdeg[i] = 1.0f / (float)(v > 0 ? v : 1);
    }
}

__global__ void fill_kernel(const int* __restrict__ src, const int* __restrict__ dst,
                            int offS, int offD, int nE) {
    int e = blockIdx.x * blockDim.x + threadIdx.x;
    if (e >= nE) return;
    int a = __ldg(src + e) + offS;
    int b = __ldg(dst + e) + offD;
    int pa = atomicAdd(&g_cur[a], 1);
    g_adj[pa] = b;
    int pb = atomicAdd(&g_cur[b], 1);
    g_adj[pb] = a;
}

// -------- gather aggregation (fp16 reads, fp32 accumulate) --------
// 8 lanes/node, each lane owns 8 half columns (16B load per neighbor).
__global__ void gather_kernel() {
    int t = blockIdx.x * blockDim.x + threadIdx.x;
    int node = t >> 3;
    if (node >= NTOT) return;
    int c = (t & 7) * 8;             // half-column offset
    int beg = g_ptr[node];
    int d   = g_deg[node];
    const __half* __restrict__ xh = g_h;
    float2 a0 = {0.f, 0.f}, a1 = {0.f, 0.f}, a2 = {0.f, 0.f}, a3 = {0.f, 0.f};
    int i = 0;
    for (; i + 4 <= d; i += 4) {
        int s0 = __ldg(g_adj + beg + i);
        int s1 = __ldg(g_adj + beg + i + 1);
        int s2 = __ldg(g_adj + beg + i + 2);
        int s3 = __ldg(g_adj + beg + i + 3);
        uint4 v0 = *(const uint4*)(xh + (size_t)s0 * HID + c);
        uint4 v1 = *(const uint4*)(xh + (size_t)s1 * HID + c);
        uint4 v2 = *(const uint4*)(xh + (size_t)s2 * HID + c);
        uint4 v3 = *(const uint4*)(xh + (size_t)s3 * HID + c);
#pragma unroll
        for (int q = 0; q < 4; q++) {
            unsigned w0 = (&v0.x)[q], w1 = (&v1.x)[q], w2 = (&v2.x)[q], w3 = (&v3.x)[q];
            float2 f0 = h2f(w0), f1 = h2f(w1), f2 = h2f(w2), f3 = h2f(w3);
            float2* acc = (q == 0) ? &a0 : (q == 1) ? &a1 : (q == 2) ? &a2 : &a3;
            acc->x += (f0.x + f1.x) + (f2.x + f3.x);
            acc->y += (f0.y + f1.y) + (f2.y + f3.y);
        }
    }
    for (; i < d; i++) {
        int s = __ldg(g_adj + beg + i);
        uint4 v = *(const uint4*)(xh + (size_t)s * HID + c);
        float2 f0 = h2f(v.x), f1 = h2f(v.y), f2 = h2f(v.z), f3 = h2f(v.w);
        a0.x += f0.x; a0.y += f0.y; a1.x += f1.x; a1.y += f1.y;
        a2.x += f2.x; a2.y += f2.y; a3.x += f3.x; a3.y += f3.y;
    }
    float rd = g_rdeg[node];
    float4 o0, o1;
    o0.x = a0.x * rd; o0.y = a0.y * rd; o0.z = a1.x * rd; o0.w = a1.y * rd;
    o1.x = a2.x * rd; o1.y = a2.y * rd; o1.z = a3.x * rd; o1.w = a3.y * rd;
    float* dst = g_agg + (size_t)node * HID + c;
    *(float4*)dst       = o0;
    *(float4*)(dst + 4) = o1;
}

// -------- fused GEMM with packed f32x2 FMAs --------
// out[n,o] = act( sum_k rowcat[n,k]*Wcat[o,k] + bias[o] (+bias2[o]) )
// rowcat = [agg_row | x_row] (bSel>=0) or plain 128-wide A row (bSel<0).
// Optionally writes fp16 shadow copy of the output row.
__global__ void __launch_bounds__(128) gemm_kernel(
        const float* __restrict__ Aext, int aSel, int lda, int bSel,
        const float* __restrict__ W0, const float* __restrict__ W1,
        const float* __restrict__ bias, const float* __restrict__ bias2,
        float* __restrict__ outExt, int outSel, int outRowOff, int relu,
        int halfOut) {
    __shared__ float Ws[64][68];
    __shared__ float rows[128][36];

    const float* __restrict__ A = (aSel == 2) ? g_agg : Aext;
    const float* __restrict__ B = (bSel == 0) ? g_x : (bSel == 1 ? g_y : nullptr);
    float* __restrict__ O = (outSel == 0) ? g_x : (outSel == 1 ? g_y : outExt);

    const int tid = threadIdx.x;
    const int tx  = tid & 15;
    const int ty  = tid >> 4;
    const int nodeBase = blockIdx.x * 32;

    for (int it = 0; it < 32; it++) {
        int node = nodeBase + it;
        int k = tid;
        float v;
        if (B) v = (k < HID) ? A[(size_t)node * lda + k]
                             : B[(size_t)node * HID + (k - HID)];
        else   v = A[(size_t)node * lda + k];
        rows[k][it] = v;
    }

    ull a01[4], a23[4];
#pragma unroll
    for (int i = 0; i < 4; i++) { a01[i] = 0ull; a23[i] = 0ull; }

    for (int h = 0; h < 2; h++) {
        __syncthreads();
        const float* Wsrc; int wstride, koff;
        if (W1) { Wsrc = h ? W1 : W0; wstride = 64;  koff = 0; }
        else    { Wsrc = W0;          wstride = 128; koff = h * 64; }
        for (int idx = tid; idx < 64 * 64; idx += 128) {
            int o = idx >> 6, k = idx & 63;
            Ws[k][o] = Wsrc[(size_t)o * wstride + koff + k];
        }
        __syncthreads();
#pragma unroll 8
        for (int k = 0; k < 64; k++) {
            ulonglong2 rp = *(const ulonglong2*)&rows[(h << 6) + k][ty * 4];
            float4 w = *(const float4*)&Ws[k][tx * 4];
            ull w0 = dup_f32(w.x), w1 = dup_f32(w.y);
            ull w2 = dup_f32(w.z), w3 = dup_f32(w.w);
            ffma2(a01[0], rp.x, w0); ffma2(a23[0], rp.y, w0);
            ffma2(a01[1], rp.x, w1); ffma2(a23[1], rp.y, w1);
            ffma2(a01[2], rp.x, w2); ffma2(a23[2], rp.y, w2);
            ffma2(a01[3], rp.x, w3); ffma2(a23[3], rp.y, w3);
        }
    }

    const int o = tx * 4;
    float b0 = bias[o], b1 = bias[o + 1], b2 = bias[o + 2], b3 = bias[o + 3];
    if (bias2) { b0 += bias2[o]; b1 += bias2[o + 1]; b2 += bias2[o + 2]; b3 += bias2[o + 3]; }

    float res[4][4];
#pragma unroll
    for (int i = 0; i < 4; i++) {
        float2 p = unpack2(a01[i]);
        float2 q = unpack2(a23[i]);
        res[0][i] = p.x; res[1][i] = p.y; res[2][i] = q.x; res[3][i] = q.y;
    }
#pragma unroll
    for (int j = 0; j < 4; j++) {
        int node = nodeBase + ty * 4 + j;
        float4 r;
        r.x = res[j][0] + b0; r.y = res[j][1] + b1;
        r.z = res[j][2] + b2; r.w = res[j][3] + b3;
        if (relu) {
            r.x = fmaxf(r.x, 0.f); r.y = fmaxf(r.y, 0.f);
            r.z = fmaxf(r.z, 0.f); r.w = fmaxf(r.w, 0.f);
        }
        *(float4*)(O + (size_t)(node + outRowOff) * HID + o) = r;
        if (halfOut) {
            uint2 hh; hh.x = f2h2(r.x, r.y); hh.y = f2h2(r.z, r.w);
            *(uint2*)(g_h + (size_t)(node + outRowOff) * HID + o) = hh;
        }
    }
}

extern "C" void kernel_launch(void* const* d_in, const int* in_sizes, int n_in,
                              void* d_out, int out_size) {
    const float* track_x   = (const float*)d_in[0];
    const int*   pl_tr_src = (const int*)d_in[1];
    const int*   pl_tr_dst = (const int*)d_in[2];
    const int*   tr_ar_src = (const int*)d_in[3];
    const int*   tr_ar_dst = (const int*)d_in[4];
    const float* pl_emb    = (const float*)d_in[5];
    const float* ar_emb    = (const float*)d_in[6];
    const float* track_W   = (const float*)d_in[7];
    const float* track_b   = (const float*)d_in[8];
    const float* type_emb  = (const float*)d_in[9];
    const float* conv_Wl   = (const float*)d_in[10];
    const float* conv_bl   = (const float*)d_in[11];
    const float* conv_Wr   = (const float*)d_in[12];
    float* out = (float*)d_out;

    const int E1 = in_sizes[1];
    const int E2 = in_sizes[3];

    // node features (fp32 + fp16 shadow)
    {
        int total = (NUM_PL + NUM_AR) * (HID / 4);
        init_emb_kernel<<<(total + 255) / 256, 256>>>(pl_emb, ar_emb, type_emb);
    }
    gemm_kernel<<<NUM_TR / 32, 128>>>(track_x, -1, 128, /*bSel*/-1,
                                      track_W, nullptr,
                                      track_b, type_emb + HID,
                                      nullptr, /*outSel*/0, OFF_TR, /*relu*/0,
                                      /*halfOut*/1);

    // degrees + CSR (fixed across layers)
    zero_deg_kernel<<<(NTOT + 255) / 256, 256>>>();
    deg_kernel<<<(E1 + 255) / 256, 256>>>(pl_tr_src, pl_tr_dst, 0, OFF_TR, E1);
    deg_kernel<<<(E2 + 255) / 256, 256>>>(tr_ar_src, tr_ar_dst, OFF_TR, OFF_AR, E2);
    scan_pass1<<<NB, SCAN_B>>>();
    scan_pass2<<<1, 256>>>();
    scan_pass3<<<NB, SCAN_B>>>();
    fill_kernel<<<(E1 + 255) / 256, 256>>>(pl_tr_src, pl_tr_dst, 0, OFF_TR, E1);
    fill_kernel<<<(E2 + 255) / 256, 256>>>(tr_ar_src, tr_ar_dst, OFF_TR, OFF_AR, E2);

    // ---- layer 0: g_x (+g_h) -> g_y (+g_h) ----
    gather_kernel<<<(NTOT * 8 + 255) / 256, 256>>>();
    gemm_kernel<<<NTOT / 32, 128>>>(nullptr, 2, HID, /*bSel*/0,
                                    conv_Wl, conv_Wr, conv_bl, nullptr,
                                    nullptr, /*outSel*/1, 0, /*relu*/1,
                                    /*halfOut*/1);

    // ---- layer 1: g_y (+g_h) -> d_out ----
    gather_kernel<<<(NTOT * 8 + 255) / 256, 256>>>();
    gemm_kernel<<<NTOT / 32, 128>>>(nullptr, 2, HID, /*bSel*/1,
                                    conv_Wl + 64 * 64, conv_Wr + 64 * 64,
                                    conv_bl + 64, nullptr,
                                    out, /*outSel*/-1, 0, /*relu*/1,
                                    /*halfOut*/0);
}